// round 9
// baseline (speedup 1.0000x reference)
#include <cuda_runtime.h>
#include <cuda_bf16.h>

// Problem dims (fixed by setup_inputs)
#define T_DIM 2048
#define N_DIM 128
#define C_DIM 96
#define NC    (N_DIM * C_DIM)
#define L_DIM 200
#define S_EXT 401            // 2*L+1
#define NWARP 4
#define NTHR  (NWARP * 32)   // 128
#define KWIN  8              // ticks per window (= barrier period)
#define SPT   4              // states per thread
#define OWNS  112            // owned slots per warp (28 threads * 4)
#define HALO  16             // left halo slots per warp (= 2*KWIN = 4 threads)
#define NREC  ((NWARP * OWNS + HALO) / SPT)   // 116 records
#define LN2   0.69314718055994530942f
#define FIXSCALE 1024.0     // fixed-point scale for the deterministic reduction

// Deterministic cross-CTA reduction state (reset by the last CTA each call).
__device__ unsigned long long g_acc  = 0ull;
__device__ unsigned int       g_done = 0u;

// One CTA per batch element. CTC forward, per-thread block-floating-point
// (4 adjacent states per thread as linear floats + power-of-two scale iM).
// In-thread FMA recurrence, one shfl/tick, one barrier per 8 ticks, depth-3
// register prefetch pipeline for the log-prob rows. The focal-weighted loss
// is reduced across CTAs IN-KERNEL: integer fixed-point atomicAdd (exactly
// associative => deterministic) + last-CTA writeback of the scalar.
__global__ __launch_bounds__(NTHR, 1)
void ctc_forward_kernel(const float* __restrict__ predicts,   // (T, N, C)
                        const int*   __restrict__ labels,     // (N, L)
                        const int*   __restrict__ preds_lengths,
                        const int*   __restrict__ label_lengths,
                        float*       __restrict__ out)
{
    const int tid  = threadIdx.x;
    const int n    = blockIdx.x;
    const int w    = tid >> 5;
    const int lane = tid & 31;
    const int sb   = OWNS * w - HALO + SPT * lane;   // first (even) slot
    const bool own = (lane >= HALO / SPT);           // lanes 0..3 are halo
    const int pidx = (sb + HALO) >> 2;               // 28*w + lane

    __shared__ float4 As[2][NREC];    // ping-pong (v0,v1,v2,v3)
    __shared__ int    Ai[2][NREC];    // ping-pong iM
    __shared__ float  Pb[2 * KWIN * C_DIM];  // linear probs, double-buffered
    __shared__ float  FinV[2];
    __shared__ int    FinI[2];

    if (tid < HALO / SPT) {           // permanent zero-pads for slots < 0
        As[0][tid] = make_float4(0.f, 0.f, 0.f, 0.f);
        As[1][tid] = make_float4(0.f, 0.f, 0.f, 0.f);
        Ai[0][tid] = 0; Ai[1][tid] = 0;
    }

    // Odd slots sb+1, sb+3 carry labels; even slots are blanks (no skip).
    int ext1 = 0, ext3 = 0;
    float sk1 = 0.0f, sk3 = 0.0f;
    {
        const int s1 = sb + 1, s3 = sb + 3;
        if (s1 >= 1 && s1 < S_EXT) {
            const int k = s1 >> 1;
            ext1 = labels[n * L_DIM + k];
            if (s1 >= 3) sk1 = (ext1 != labels[n * L_DIM + k - 1]) ? 1.0f : 0.0f;
        }
        if (s3 >= 1 && s3 < S_EXT) {
            const int k = s3 >> 1;
            ext3 = labels[n * L_DIM + k];
            if (s3 >= 3) sk3 = (ext3 != labels[n * L_DIM + k - 1]) ? 1.0f : 0.0f;
        }
    }
    const int len = preds_lengths[n];
    const int end = 2 * label_lengths[n];

    // Cooperative staging geometry: 8 rows x 96 classes = 768 floats, 6/thread.
    const float* gptr[6]; int r_q[6];
#pragma unroll
    for (int q = 0; q < 6; ++q) {
        const int idx = tid + q * NTHR;
        const int r = idx / C_DIM, c = idx - r * C_DIM;
        r_q[q]  = r;
        gptr[q] = predicts + (size_t)r * NC + (size_t)n * C_DIM + c;
    }

    // Pre-stage rows [0,8) into buffer 0; prime the depth-3 pipeline
    // with LDGs for windows 1..3 (rows 8..31; len >= 1024 so always valid).
    float stgA[6], stgB[6], stgC[6];
#pragma unroll
    for (int q = 0; q < 6; ++q) {
        Pb[tid + q * NTHR] = __expf(__ldg(gptr[q]));
        stgA[q] = __ldg(gptr[q] + (size_t)(1 * KWIN) * NC);
        stgB[q] = __ldg(gptr[q] + (size_t)(2 * KWIN) * NC);
        stgC[q] = __ldg(gptr[q] + (size_t)(3 * KWIN) * NC);
    }
    __syncthreads();

    float v0 = (sb == 0) ? 1.0f : 0.0f;   // virtual alpha_{-1}: 1 at slot 0
    float v1 = 0.0f, v2 = 0.0f, v3 = 0.0f;
    int   iM = 0;
    float fp = (lane == 0) ? 0.0f : 1.0f; // all scales equal at t=0
    const int nwin = (len + KWIN - 1) >> 3;   // len uniform per CTA

    for (int win = 0; win < nwin; ++win) {
        const int t0 = win << 3;

        const float* prow = Pb + ((win & 1) ? KWIN * C_DIM : 0);
#pragma unroll
        for (int j = 0; j < KWIN; ++j) {
            const int t = t0 + j;
            const float P0 = prow[0];        // both even slots are blanks
            const float P1 = prow[ext1];
            const float P3 = prow[ext3];

            const float vp3 = __shfl_up_sync(0xffffffffu, v3, 1);
            const float vp  = vp3 * fp;      // fp==0 masks lane 0

            const float nv0 = (v0 + vp) * P0;
            const float nv1 = (v1 + v0 + vp * sk1) * P1;
            const float nv2 = (v2 + v1) * P0;
            const float nv3 = (v3 + v2 + v1 * sk3) * P3;
            v0 = nv0; v1 = nv1; v2 = nv2; v3 = nv3;
            prow += C_DIM;

            if (t == len - 1 && own) {       // record final states (owners only)
                if (sb == end)         { FinV[0] = v0; FinI[0] = iM; }
                if (sb + 2 == end)     { FinV[0] = v2; FinI[0] = iM; }
                if (sb + 1 == end - 1) { FinV[1] = v1; FinI[1] = iM; }
                if (sb + 3 == end - 1) { FinV[1] = v3; FinI[1] = iM; }
            }
        }

        // Commit the set holding window win+1's rows (LDG issued 3 windows
        // ago), then reuse that set's registers for window win+4's rows.
        {
            float* dst = Pb + ((win & 1) ? 0 : KWIN * C_DIM);
            const int tnext = (win + 4) * KWIN;
            const int set   = win % 3;
            if (set == 0) {
#pragma unroll
                for (int q = 0; q < 6; ++q) {
                    dst[tid + q * NTHR] = __expf(stgA[q]);
                    stgA[q] = (tnext + r_q[q] < T_DIM)
                              ? __ldg(gptr[q] + (size_t)tnext * NC) : 0.0f;
                }
            } else if (set == 1) {
#pragma unroll
                for (int q = 0; q < 6; ++q) {
                    dst[tid + q * NTHR] = __expf(stgB[q]);
                    stgB[q] = (tnext + r_q[q] < T_DIM)
                              ? __ldg(gptr[q] + (size_t)tnext * NC) : 0.0f;
                }
            } else {
#pragma unroll
                for (int q = 0; q < 6; ++q) {
                    dst[tid + q * NTHR] = __expf(stgC[q]);
                    stgC[q] = (tnext + r_q[q] < T_DIM)
                              ? __ldg(gptr[q] + (size_t)tnext * NC) : 0.0f;
                }
            }
        }

        // ---- window boundary ----
        // 1) per-thread renorm: pull exponent of max(v0..v3) into iM.
        const float mx = fmaxf(fmaxf(v0, v1), fmaxf(v2, v3));
        if (mx > 0.0f) {
            const int e = (int)(__float_as_uint(mx) >> 23) - 127;
            iM += e;
            const float sc = __int_as_float((unsigned)(127 - e) << 23);
            v0 *= sc; v1 *= sc; v2 *= sc; v3 *= sc;
        }
        // 2) owners publish; barrier; everyone reloads their record.
        const int ab = win & 1;
        if (own) {
            As[ab][pidx] = make_float4(v0, v1, v2, v3);
            Ai[ab][pidx] = iM;
        }
        __syncthreads();
        const float4 pv = As[ab][pidx];
        v0 = pv.x; v1 = pv.y; v2 = pv.z; v3 = pv.w;
        iM = Ai[ab][pidx];

        // 3) unreached threads adopt a propagated scale (4 records back).
        if (fmaxf(fmaxf(v0, v1), fmaxf(v2, v3)) == 0.0f)
            iM = Ai[ab][(pidx >= 4) ? (pidx - 4) : 0];

        // 4) fixed per-window neighbor rescale from post-adoption scales.
        const int iMp = __shfl_up_sync(0xffffffffu, iM, 1);
        int k = iMp - iM;
        k = (k > 125) ? 125 : ((k < -127) ? -127 : k);
        fp = __int_as_float((unsigned)(k + 127) << 23);  // k=-127 -> exact 0
        if (lane == 0) fp = 0.0f;
    }

    __syncthreads();
    if (tid == 0) {
        const float f0 = __log2f(FinV[0]) + (float)FinI[0];
        const float f1 = __log2f(FinV[1]) + (float)FinI[1];
        const float mm   = fmaxf(f0, f1);
        const float fin2 = mm + __log2f(exp2f(f0 - mm) + exp2f(f1 - mm));
        const float ctc  = -(fin2 * LN2);
        const float fw   = 1.0f - __expf(-ctc);     // focal: alpha=1, gamma=2
        const double contrib = (double)(ctc * (fw * fw));

        // Deterministic reduction: integer fixed-point atomic (exactly
        // associative), last CTA converts + writes + resets for next replay.
        const unsigned long long q =
            (unsigned long long)(long long)(contrib * FIXSCALE + 0.5);
        atomicAdd(&g_acc, q);
        __threadfence();
        const unsigned rank = atomicAdd(&g_done, 1u);
        if (rank == N_DIM - 1) {
            const unsigned long long total = atomicAdd(&g_acc, 0ull);
            out[0] = (float)((double)total / FIXSCALE);
            g_acc  = 0ull;          // reset for the next graph replay
            g_done = 0u;
        }
    }
}

extern "C" void kernel_launch(void* const* d_in, const int* in_sizes, int n_in,
                              void* d_out, int out_size)
{
    const float* predicts      = (const float*)d_in[0];
    const int*   labels        = (const int*)  d_in[1];
    // d_in[2] = ref_labels (unused), d_in[5] = ref_length (unused)
    const int*   preds_lengths = (const int*)  d_in[3];
    const int*   label_lengths = (const int*)  d_in[4];
    float*       out           = (float*)d_out;

    ctc_forward_kernel<<<N_DIM, NTHR>>>(predicts, labels, preds_lengths,
                                        label_lengths, out);
}

// round 10
// speedup vs baseline: 1.2742x; 1.2742x over previous
#include <cuda_runtime.h>
#include <cuda_bf16.h>

// Problem dims (fixed by setup_inputs)
#define T_DIM 2048
#define N_DIM 128
#define C_DIM 96
#define NC    (N_DIM * C_DIM)
#define L_DIM 200
#define S_EXT 401            // 2*L+1
#define NWARP 4
#define NTHR  (NWARP * 32)   // 128
#define KWIN  8              // ticks per window (= barrier period)
#define SPT   4              // states per thread
#define OWNS  112            // owned slots per warp (28 threads * 4)
#define HALO  16             // left halo slots per warp (= 2*KWIN = 4 threads)
#define NREC  ((NWARP * OWNS + HALO) / SPT)   // 116 records
#define LN2   0.69314718055994530942f
#define FIXSCALE 1024.0      // fixed-point scale for deterministic reduction

// Deterministic cross-CTA reduction state (reset by the last CTA each call).
__device__ unsigned long long g_acc  = 0ull;
__device__ unsigned int       g_done = 0u;

// One CTA per batch element. CTC forward, per-thread block-floating-point
// (4 adjacent states per thread, linear floats + power-of-two scale iM).
// R10: all memory ops pulled off the loop-carried chain -- per-window P
// values are gathered into registers right after the barrier, the SMEM
// commit runs at window TOP (independent of alpha), and the boundary's
// adoption load issues in parallel with the main reload. Inner tick is
// 1 shfl + 8 FMA, pure register dataflow.
__global__ __launch_bounds__(NTHR, 1)
void ctc_forward_kernel(const float* __restrict__ predicts,   // (T, N, C)
                        const int*   __restrict__ labels,     // (N, L)
                        const int*   __restrict__ preds_lengths,
                        const int*   __restrict__ label_lengths,
                        float*       __restrict__ out)
{
    const int tid  = threadIdx.x;
    const int n    = blockIdx.x;
    const int w    = tid >> 5;
    const int lane = tid & 31;
    const int sb   = OWNS * w - HALO + SPT * lane;   // first (even) slot
    const bool own = (lane >= HALO / SPT);           // lanes 0..3 are halo
    const int pidx = (sb + HALO) >> 2;               // 28*w + lane

    __shared__ float4 As[2][NREC];    // ping-pong (v0,v1,v2,v3)
    __shared__ int    Ai[2][NREC];    // ping-pong iM
    __shared__ float  Pb[2 * KWIN * C_DIM];  // linear probs, double-buffered
    __shared__ float  FinV[2];
    __shared__ int    FinI[2];

    if (tid < HALO / SPT) {           // permanent zero-pads for slots < 0
        As[0][tid] = make_float4(0.f, 0.f, 0.f, 0.f);
        As[1][tid] = make_float4(0.f, 0.f, 0.f, 0.f);
        Ai[0][tid] = 0; Ai[1][tid] = 0;
    }

    // Odd slots sb+1, sb+3 carry labels; even slots are blanks (no skip).
    int ext1 = 0, ext3 = 0;
    float sk1 = 0.0f, sk3 = 0.0f;
    {
        const int s1 = sb + 1, s3 = sb + 3;
        if (s1 >= 1 && s1 < S_EXT) {
            const int k = s1 >> 1;
            ext1 = labels[n * L_DIM + k];
            if (s1 >= 3) sk1 = (ext1 != labels[n * L_DIM + k - 1]) ? 1.0f : 0.0f;
        }
        if (s3 >= 1 && s3 < S_EXT) {
            const int k = s3 >> 1;
            ext3 = labels[n * L_DIM + k];
            if (s3 >= 3) sk3 = (ext3 != labels[n * L_DIM + k - 1]) ? 1.0f : 0.0f;
        }
    }
    const int len     = preds_lengths[n];
    const int end     = 2 * label_lengths[n];
    const int lastwin = (len - 1) >> 3;

    // Cooperative staging geometry: 8 rows x 96 classes = 768 floats, 6/thread.
    const float* gptr[6]; int r_q[6];
#pragma unroll
    for (int q = 0; q < 6; ++q) {
        const int idx = tid + q * NTHR;
        const int r = idx / C_DIM, c = idx - r * C_DIM;
        r_q[q]  = r;
        gptr[q] = predicts + (size_t)r * NC + (size_t)n * C_DIM + c;
    }

    // Pre-stage rows [0,8) into buffer 0; prime the depth-3 register pipeline
    // with LDGs for windows 1..3 (rows 8..31; len >= 1024 so always valid).
    float stgA[6], stgB[6], stgC[6];
#pragma unroll
    for (int q = 0; q < 6; ++q) {
        Pb[tid + q * NTHR] = __expf(__ldg(gptr[q]));
        stgA[q] = __ldg(gptr[q] + (size_t)(1 * KWIN) * NC);
        stgB[q] = __ldg(gptr[q] + (size_t)(2 * KWIN) * NC);
        stgC[q] = __ldg(gptr[q] + (size_t)(3 * KWIN) * NC);
    }
    __syncthreads();

    float v0 = (sb == 0) ? 1.0f : 0.0f;   // virtual alpha_{-1}: 1 at slot 0
    float v1 = 0.0f, v2 = 0.0f, v3 = 0.0f;
    int   iM = 0;
    float fp = (lane == 0) ? 0.0f : 1.0f; // all scales equal at t=0
    const int nwin = (len + KWIN - 1) >> 3;   // len uniform per CTA

    for (int win = 0; win < nwin; ++win) {
        // --- window top: gather this window's P values into registers ---
        // (depends only on the buffer committed last window; latency overlaps
        //  the first ticks instead of sitting on the carried chain)
        const float* prow = Pb + ((win & 1) ? KWIN * C_DIM : 0);
        float g0[KWIN], g1[KWIN], g3[KWIN];
#pragma unroll
        for (int j = 0; j < KWIN; ++j) {
            g0[j] = prow[j * C_DIM];          // blank (broadcast, conflict-free)
            g1[j] = prow[j * C_DIM + ext1];   // gather
            g3[j] = prow[j * C_DIM + ext3];   // gather
        }

        // --- commit next window's rows into the OTHER buffer (independent of
        //     alpha; runs concurrently with the tick loop below), then refill
        //     the staging set with rows 4 windows ahead ---
        {
            float* dst = Pb + ((win & 1) ? 0 : KWIN * C_DIM);
            const int tnext = (win + 4) * KWIN;
            const int set   = win % 3;
            if (set == 0) {
#pragma unroll
                for (int q = 0; q < 6; ++q) {
                    dst[tid + q * NTHR] = __expf(stgA[q]);
                    stgA[q] = (tnext + r_q[q] < T_DIM)
                              ? __ldg(gptr[q] + (size_t)tnext * NC) : 0.0f;
                }
            } else if (set == 1) {
#pragma unroll
                for (int q = 0; q < 6; ++q) {
                    dst[tid + q * NTHR] = __expf(stgB[q]);
                    stgB[q] = (tnext + r_q[q] < T_DIM)
                              ? __ldg(gptr[q] + (size_t)tnext * NC) : 0.0f;
                }
            } else {
#pragma unroll
                for (int q = 0; q < 6; ++q) {
                    dst[tid + q * NTHR] = __expf(stgC[q]);
                    stgC[q] = (tnext + r_q[q] < T_DIM)
                              ? __ldg(gptr[q] + (size_t)tnext * NC) : 0.0f;
                }
            }
        }

        // --- tick loop: pure register dataflow (1 shfl + 8 FMA per tick) ---
        if (win != lastwin) {
#pragma unroll
            for (int j = 0; j < KWIN; ++j) {
                const float vp3 = __shfl_up_sync(0xffffffffu, v3, 1);
                const float vp  = vp3 * fp;      // fp==0 masks lane 0
                const float nv0 = (v0 + vp) * g0[j];
                const float nv1 = (v1 + v0 + vp * sk1) * g1[j];
                const float nv2 = (v2 + v1) * g0[j];
                const float nv3 = (v3 + v2 + v1 * sk3) * g3[j];
                v0 = nv0; v1 = nv1; v2 = nv2; v3 = nv3;
            }
        } else {
#pragma unroll
            for (int j = 0; j < KWIN; ++j) {
                const int t = (win << 3) + j;
                const float vp3 = __shfl_up_sync(0xffffffffu, v3, 1);
                const float vp  = vp3 * fp;
                const float nv0 = (v0 + vp) * g0[j];
                const float nv1 = (v1 + v0 + vp * sk1) * g1[j];
                const float nv2 = (v2 + v1) * g0[j];
                const float nv3 = (v3 + v2 + v1 * sk3) * g3[j];
                v0 = nv0; v1 = nv1; v2 = nv2; v3 = nv3;

                if (t == len - 1 && own) {       // record final states
                    if (sb == end)         { FinV[0] = v0; FinI[0] = iM; }
                    if (sb + 2 == end)     { FinV[0] = v2; FinI[0] = iM; }
                    if (sb + 1 == end - 1) { FinV[1] = v1; FinI[1] = iM; }
                    if (sb + 3 == end - 1) { FinV[1] = v3; FinI[1] = iM; }
                }
            }
        }

        // ---- window boundary ----
        // 1) per-thread renorm: pull exponent of max(v0..v3) into iM.
        const float mx = fmaxf(fmaxf(v0, v1), fmaxf(v2, v3));
        if (mx > 0.0f) {
            const int e = (int)(__float_as_uint(mx) >> 23) - 127;
            iM += e;
            const float sc = __int_as_float((unsigned)(127 - e) << 23);
            v0 *= sc; v1 *= sc; v2 *= sc; v3 *= sc;
        }
        // 2) owners publish; barrier; reload record + adoption scale in parallel.
        const int ab = win & 1;
        if (own) {
            As[ab][pidx] = make_float4(v0, v1, v2, v3);
            Ai[ab][pidx] = iM;
        }
        __syncthreads();
        const float4 pv   = As[ab][pidx];
        const int    iMr  = Ai[ab][pidx];
        const int    iMa  = Ai[ab][(pidx >= 4) ? (pidx - 4) : 0];  // parallel load
        v0 = pv.x; v1 = pv.y; v2 = pv.z; v3 = pv.w;
        // 3) unreached threads adopt the propagated scale (select, no extra hop).
        iM = (fmaxf(fmaxf(v0, v1), fmaxf(v2, v3)) == 0.0f) ? iMa : iMr;

        // 4) fixed per-window neighbor rescale from post-adoption scales.
        const int iMp = __shfl_up_sync(0xffffffffu, iM, 1);
        int k = iMp - iM;
        k = (k > 125) ? 125 : ((k < -127) ? -127 : k);
        fp = __int_as_float((unsigned)(k + 127) << 23);  // k=-127 -> exact 0
        if (lane == 0) fp = 0.0f;
    }

    __syncthreads();
    if (tid == 0) {
        const float f0 = __log2f(FinV[0]) + (float)FinI[0];
        const float f1 = __log2f(FinV[1]) + (float)FinI[1];
        const float mm   = fmaxf(f0, f1);
        const float fin2 = mm + __log2f(exp2f(f0 - mm) + exp2f(f1 - mm));
        const float ctc  = -(fin2 * LN2);
        const float fw   = 1.0f - __expf(-ctc);     // focal: alpha=1, gamma=2
        const double contrib = (double)(ctc * (fw * fw));

        // Deterministic reduction: integer fixed-point atomic (exactly
        // associative), last CTA converts + writes + resets for next replay.
        const unsigned long long q =
            (unsigned long long)(long long)(contrib * FIXSCALE + 0.5);
        atomicAdd(&g_acc, q);
        __threadfence();
        const unsigned rank = atomicAdd(&g_done, 1u);
        if (rank == N_DIM - 1) {
            const unsigned long long total = atomicAdd(&g_acc, 0ull);
            out[0] = (float)((double)total / FIXSCALE);
            g_acc  = 0ull;          // reset for the next graph replay
            g_done = 0u;
        }
    }
}

extern "C" void kernel_launch(void* const* d_in, const int* in_sizes, int n_in,
                              void* d_out, int out_size)
{
    const float* predicts      = (const float*)d_in[0];
    const int*   labels        = (const int*)  d_in[1];
    // d_in[2] = ref_labels (unused), d_in[5] = ref_length (unused)
    const int*   preds_lengths = (const int*)  d_in[3];
    const int*   label_lengths = (const int*)  d_in[4];
    float*       out           = (float*)d_out;

    ctc_forward_kernel<<<N_DIM, NTHR>>>(predicts, labels, preds_lengths,
                                        label_lengths, out);
}